// round 8
// baseline (speedup 1.0000x reference)
#include <cuda_runtime.h>
#include <cuda_bf16.h>
#include <math.h>

#define N_NODES 50000
#define N_EDGES 800000
#define F_IN    128
#define HID     64
#define HEADS   4
#define NGRAPH  512
#define CLASSES 2
#define NB_SCAN ((N_NODES + 1023) >> 10)   // 49

// ---------------- scratch (static device globals; no allocation) ----------------
__device__ float g_h[(size_t)N_NODES * 256];     // GCN hs [N,64] / GAT y [N,256]
__device__ float g_x[(size_t)N_NODES * HID];
__device__ int   g_counts[N_NODES];
__device__ int   g_rowptr[N_NODES + 1];
__device__ int   g_cursor[N_NODES];
__device__ int   g_csrsrc[N_EDGES];
__device__ int   g_bsums[64];
__device__ int   g_boff[65];
__device__ int   g_bcnt[NGRAPH];
__device__ int   g_bptr[NGRAPH + 1];
__device__ float g_dinv[N_NODES];
__device__ float g_asrc[N_NODES * HEADS];
__device__ float g_adst[N_NODES * HEADS];
__device__ float g_uv[512];                      // u[4][64] then v[4][64]

// ---------------- helpers ----------------
__device__ __forceinline__ float leaky02(float v) { return v > 0.f ? v : 0.2f * v; }

__device__ __forceinline__ unsigned long long packdup(float x) {
    unsigned long long r;
    asm("mov.b64 %0, {%1, %1};" : "=l"(r) : "f"(x));
    return r;
}
__device__ __forceinline__ void ffma2(unsigned long long& d, unsigned long long a, unsigned long long b) {
    asm("fma.rn.f32x2 %0, %1, %2, %3;" : "=l"(d) : "l"(a), "l"(b), "l"(d));
}
__device__ __forceinline__ float2 unpack2(unsigned long long v) {
    float2 r;
    asm("mov.b64 {%0, %1}, %2;" : "=f"(r.x), "=f"(r.y) : "l"(v));
    return r;
}

// ---------------- init / CSR build ----------------
__global__ void zero_kernel(int* a, int na, int* b, int nb) {
    int i = blockIdx.x * blockDim.x + threadIdx.x;
    if (i < na) a[i] = 0;
    if (i < nb) b[i] = 0;
}
__global__ void hist_kernel(const int* __restrict__ dst, int* cnt,
                            const int* __restrict__ batch, int* bcnt, int E, int N) {
    int e = blockIdx.x * blockDim.x + threadIdx.x;
    if (e < E) atomicAdd(&cnt[dst[e]], 1);
    if (e < N) atomicAdd(&bcnt[batch[e]], 1);
}

// u_h = W_h @ att_src[h], v_h = W_h @ att_dst[h]  (one 256-thread block)
__global__ __launch_bounds__(256) void uv_kernel(
    const float* __restrict__ gat_w, const float* __restrict__ att_s,
    const float* __restrict__ att_d, float* __restrict__ uv)
{
    int t = threadIdx.x;
    int h = t >> 6, k = t & 63;
    const float* wrow = gat_w + (size_t)k * 256 + h * 64;
    const float* as = att_s + h * 64;
    const float* ad = att_d + h * 64;
    float su = 0.f, sv = 0.f;
#pragma unroll 8
    for (int c = 0; c < 64; c++) {
        float w = wrow[c];
        su = fmaf(w, as[c], su);
        sv = fmaf(w, ad[c], sv);
    }
    uv[h * 64 + k] = su;
    uv[256 + h * 64 + k] = sv;
}

// per-1024-chunk local exclusive scan + block sums + dinv (fused)
__global__ __launch_bounds__(1024) void scan_local_kernel(
    const int* __restrict__ counts, int* rowptr, int* bsums, float* dinv, int n)
{
    __shared__ int wsum[32];
    int tid = threadIdx.x, lane = tid & 31, wid = tid >> 5;
    int idx = blockIdx.x * 1024 + tid;
    int v = (idx < n) ? counts[idx] : 0;
    if (idx < n) dinv[idx] = rsqrtf((float)(v + 1));
    int inc = v;
#pragma unroll
    for (int o = 1; o < 32; o <<= 1) {
        int t = __shfl_up_sync(0xffffffffu, inc, o);
        if (lane >= o) inc += t;
    }
    if (lane == 31) wsum[wid] = inc;
    __syncthreads();
    if (wid == 0) {
        int wi = wsum[lane];
#pragma unroll
        for (int o = 1; o < 32; o <<= 1) {
            int t = __shfl_up_sync(0xffffffffu, wi, o);
            if (lane >= o) wi += t;
        }
        wsum[lane] = wi;
    }
    __syncthreads();
    int excl = inc - v + (wid ? wsum[wid - 1] : 0);
    if (idx < n) rowptr[idx] = excl;
    if (tid == 1023) bsums[blockIdx.x] = excl + v;
}

// two independent small exclusive scans in one launch
__global__ __launch_bounds__(1024) void scan_small2_kernel(
    const int* __restrict__ in0, int* out0, int n0,
    const int* __restrict__ in1, int* out1, int n1)
{
    __shared__ int wsum[32];
    const int* in = blockIdx.x ? in1 : in0;
    int*      out = blockIdx.x ? out1 : out0;
    int         n = blockIdx.x ? n1 : n0;
    int tid = threadIdx.x, lane = tid & 31, wid = tid >> 5;
    int v = (tid < n) ? in[tid] : 0;
    int inc = v;
#pragma unroll
    for (int o = 1; o < 32; o <<= 1) {
        int t = __shfl_up_sync(0xffffffffu, inc, o);
        if (lane >= o) inc += t;
    }
    if (lane == 31) wsum[wid] = inc;
    __syncthreads();
    if (wid == 0) {
        int wi = wsum[lane];
#pragma unroll
        for (int o = 1; o < 32; o <<= 1) {
            int t = __shfl_up_sync(0xffffffffu, wi, o);
            if (lane >= o) wi += t;
        }
        wsum[lane] = wi;
    }
    __syncthreads();
    int excl = inc - v + (wid ? wsum[wid - 1] : 0);
    if (tid < n) out[tid] = excl;
    if (tid == n - 1) out[n] = excl + v;
}

__global__ void scan_apply_kernel(int* rowptr, int* cursor, const int* __restrict__ boff, int n) {
    int idx = blockIdx.x * blockDim.x + threadIdx.x;
    if (idx < n) {
        int r = rowptr[idx] + boff[idx >> 10];
        rowptr[idx] = r;
        cursor[idx] = r;
    }
    if (idx == n) rowptr[n] = boff[NB_SCAN];
}

__global__ void scatter_kernel(const int* __restrict__ src, const int* __restrict__ dst,
                               int* cursor, int* __restrict__ csr, int E)
{
    int e = blockIdx.x * blockDim.x + threadIdx.x;
    if (e >= E) return;
    int p = atomicAdd(&cursor[dst[e]], 1);
    csr[p] = src[e];
}

// ---------------- GEMM: Y = X(N,K) @ W -> [N,64], BM=64, 256 thr, 2x8 tile ----------------
template <int K, bool SCALE, bool PERMW, bool RELUB>
__global__ __launch_bounds__(256) void gemm256(
    const float* __restrict__ X, const float* __restrict__ W,
    float* __restrict__ Y, int ldy, const float* __restrict__ dinv,
    const float* __restrict__ bias, int n)
{
    __shared__ float Xs[16][64];
    __shared__ float Ws[16][64];
    int tid = threadIdx.x;
    int tx = tid & 7;        // col group: cols tx*8 .. +7
    int ty = tid >> 3;       // 0..31  : rows ty*2, ty*2+1
    int row0 = blockIdx.x * 64;

    unsigned long long acc2[2][4];
#pragma unroll
    for (int i = 0; i < 2; i++)
#pragma unroll
        for (int j = 0; j < 4; j++) acc2[i][j] = 0ull;

    int lrow = tid >> 2;      // 0..63 (staged row)
    int lq   = tid & 3;       // which float4 of the 16-k chunk
    int xrow = min(row0 + lrow, n - 1);
    const float4* xr = reinterpret_cast<const float4*>(X + (size_t)xrow * K);

    int wk = tid >> 4;        // 0..15
    int wc = (tid & 15) * 4;  // 0..60

    for (int k0 = 0; k0 < K; k0 += 16) {
        float4 a = xr[(k0 >> 2) + lq];
        int kb = lq * 4;
        Xs[kb + 0][lrow] = a.x; Xs[kb + 1][lrow] = a.y;
        Xs[kb + 2][lrow] = a.z; Xs[kb + 3][lrow] = a.w;
        if (PERMW) {
            int k = k0 + wk;
            int c = k & 63, hh = k >> 6;
            *reinterpret_cast<float4*>(&Ws[wk][wc]) =
                *reinterpret_cast<const float4*>(&W[(size_t)c * 256 + hh * 64 + wc]);
        } else {
            *reinterpret_cast<float4*>(&Ws[wk][wc]) =
                *reinterpret_cast<const float4*>(&W[(size_t)(k0 + wk) * 64 + wc]);
        }
        __syncthreads();
#pragma unroll
        for (int k = 0; k < 16; k++) {
            float2 xv = *reinterpret_cast<const float2*>(&Xs[k][ty * 2]);
            const unsigned long long* wp = reinterpret_cast<const unsigned long long*>(&Ws[k][tx * 8]);
            unsigned long long w0 = wp[0], w1 = wp[1], w2 = wp[2], w3 = wp[3];
            unsigned long long xd;
            xd = packdup(xv.x);
            ffma2(acc2[0][0], xd, w0); ffma2(acc2[0][1], xd, w1);
            ffma2(acc2[0][2], xd, w2); ffma2(acc2[0][3], xd, w3);
            xd = packdup(xv.y);
            ffma2(acc2[1][0], xd, w0); ffma2(acc2[1][1], xd, w1);
            ffma2(acc2[1][2], xd, w2); ffma2(acc2[1][3], xd, w3);
        }
        __syncthreads();
    }

    float bv[8];
    if (RELUB) {
#pragma unroll
        for (int j = 0; j < 8; j++) bv[j] = bias[tx * 8 + j];
    }

#pragma unroll
    for (int i = 0; i < 2; i++) {
        int r = row0 + ty * 2 + i;
        float v[8];
#pragma unroll
        for (int jp = 0; jp < 4; jp++) {
            float2 p = unpack2(acc2[i][jp]);
            v[jp * 2] = p.x; v[jp * 2 + 1] = p.y;
        }
        if (r < n) {
            if (SCALE) {
                float s = dinv[r];
#pragma unroll
                for (int j = 0; j < 8; j++) v[j] *= s;
            }
            if (RELUB) {
#pragma unroll
                for (int j = 0; j < 8; j++) v[j] = fmaxf(fmaf(v[j], 0.25f, bv[j]), 0.f);
            }
            float* yr = Y + (size_t)r * ldy + tx * 8;
            reinterpret_cast<float4*>(yr)[0] = make_float4(v[0], v[1], v[2], v[3]);
            reinterpret_cast<float4*>(yr)[1] = make_float4(v[4], v[5], v[6], v[7]);
        }
    }
}

// ---------------- GCN gather (half-warp per edge, float4 lanes) ----------------
template <bool ATT>
__global__ __launch_bounds__(256) void gcn_gather_kernel(
    const float* __restrict__ hs, const int* __restrict__ rowptr, const int* __restrict__ csr,
    const float* __restrict__ dinv, const float* __restrict__ bias,
    float* __restrict__ xout, const float* __restrict__ uv,
    float* __restrict__ asrc, float* __restrict__ adst, int n)
{
    __shared__ float4 suv[128];
    if (ATT) {
        if (threadIdx.x < 128)
            suv[threadIdx.x] = reinterpret_cast<const float4*>(uv)[threadIdx.x];
        __syncthreads();
    }

    int w = (blockIdx.x * blockDim.x + threadIdx.x) >> 5;
    if (w >= n) return;
    int lane = threadIdx.x & 31;
    int half = lane >> 4, c = lane & 15;
    int beg = rowptr[w], end = rowptr[w + 1];
    const float4* h4 = reinterpret_cast<const float4*>(hs);
    float4 acc = make_float4(0.f, 0.f, 0.f, 0.f);
    const float4 z4 = make_float4(0.f, 0.f, 0.f, 0.f);

    for (int base = beg; base < end; base += 32) {
        int m = min(32, end - base);
        int sreg = (base + lane < end) ? csr[base + lane] : 0;
        for (int i = 0; i < m; i += 4) {
            int e0 = i + half, e1 = i + 2 + half;
            int s0 = __shfl_sync(0xffffffffu, sreg, e0);
            int s1 = __shfl_sync(0xffffffffu, sreg, e1);
            float4 a = (e0 < m) ? h4[(size_t)s0 * 16 + c] : z4;
            float4 b = (e1 < m) ? h4[(size_t)s1 * 16 + c] : z4;
            acc.x += a.x + b.x; acc.y += a.y + b.y;
            acc.z += a.z + b.z; acc.w += a.w + b.w;
        }
    }
    acc.x += __shfl_xor_sync(0xffffffffu, acc.x, 16);
    acc.y += __shfl_xor_sync(0xffffffffu, acc.y, 16);
    acc.z += __shfl_xor_sync(0xffffffffu, acc.z, 16);
    acc.w += __shfl_xor_sync(0xffffffffu, acc.w, 16);

    float4 sv = h4[(size_t)w * 16 + c];
    float dw = dinv[w];
    float4 bv = reinterpret_cast<const float4*>(bias)[c];
    float4 o;
    o.x = fmaxf((acc.x + sv.x) * dw + bv.x, 0.f);
    o.y = fmaxf((acc.y + sv.y) * dw + bv.y, 0.f);
    o.z = fmaxf((acc.z + sv.z) * dw + bv.z, 0.f);
    o.w = fmaxf((acc.w + sv.w) * dw + bv.w, 0.f);
    if (lane < 16)
        reinterpret_cast<float4*>(xout + (size_t)w * HID)[c] = o;

    if (ATT) {
        float4 od = (lane < 16) ? o : z4;
        float d8[8];
#pragma unroll
        for (int h = 0; h < 8; h++) {
            float4 u = suv[h * 16 + c];
            d8[h] = od.x * u.x + od.y * u.y + od.z * u.z + od.w * u.w;
        }
#pragma unroll
        for (int off = 16; off > 0; off >>= 1) {
#pragma unroll
            for (int h = 0; h < 8; h++)
                d8[h] += __shfl_xor_sync(0xffffffffu, d8[h], off);
        }
        if (lane == 0) {
            reinterpret_cast<float4*>(asrc)[w] = make_float4(d8[0], d8[1], d8[2], d8[3]);
            reinterpret_cast<float4*>(adst)[w] = make_float4(d8[4], d8[5], d8[6], d8[7]);
        }
    }
}

// ---------------- GAT gather (x-space, half-warp per edge) ----------------
__global__ __launch_bounds__(256) void gat_gather_kernel(
    const float* __restrict__ x, const float* __restrict__ asrc, const float* __restrict__ adst,
    const int* __restrict__ rowptr, const int* __restrict__ csr,
    float* __restrict__ y, int n)
{
    int w = (blockIdx.x * blockDim.x + threadIdx.x) >> 5;
    if (w >= n) return;
    int lane = threadIdx.x & 31;
    int half = lane >> 4, c = lane & 15;
    int beg = rowptr[w], end = rowptr[w + 1];

    float4 adv = reinterpret_cast<const float4*>(adst)[w];
    const float4* x4 = reinterpret_cast<const float4*>(x);
    const float4* as4 = reinterpret_cast<const float4*>(asrc);
    const float4 z4 = make_float4(0.f, 0.f, 0.f, 0.f);

    float4 y0 = z4, y1 = z4, y2 = z4, y3 = z4;
    float den0 = 0.f, den1 = 0.f, den2 = 0.f, den3 = 0.f;

    for (int base = beg; base < end; base += 32) {
        int m = min(32, end - base);
        bool valid = (base + lane < end);
        int sreg = valid ? csr[base + lane] : 0;
        float4 as = as4[sreg];
        float p0 = valid ? expf(leaky02(as.x + adv.x)) : 0.f;
        float p1 = valid ? expf(leaky02(as.y + adv.y)) : 0.f;
        float p2 = valid ? expf(leaky02(as.z + adv.z)) : 0.f;
        float p3 = valid ? expf(leaky02(as.w + adv.w)) : 0.f;
        den0 += p0; den1 += p1; den2 += p2; den3 += p3;
#pragma unroll 2
        for (int i = 0; i < m; i += 2) {
            int e = i + half;
            int   s  = __shfl_sync(0xffffffffu, sreg, e);
            float q0 = __shfl_sync(0xffffffffu, p0, e);
            float q1 = __shfl_sync(0xffffffffu, p1, e);
            float q2 = __shfl_sync(0xffffffffu, p2, e);
            float q3 = __shfl_sync(0xffffffffu, p3, e);
            float4 xv = (e < m) ? x4[(size_t)s * 16 + c] : z4;
            y0.x = fmaf(q0, xv.x, y0.x); y0.y = fmaf(q0, xv.y, y0.y);
            y0.z = fmaf(q0, xv.z, y0.z); y0.w = fmaf(q0, xv.w, y0.w);
            y1.x = fmaf(q1, xv.x, y1.x); y1.y = fmaf(q1, xv.y, y1.y);
            y1.z = fmaf(q1, xv.z, y1.z); y1.w = fmaf(q1, xv.w, y1.w);
            y2.x = fmaf(q2, xv.x, y2.x); y2.y = fmaf(q2, xv.y, y2.y);
            y2.z = fmaf(q2, xv.z, y2.z); y2.w = fmaf(q2, xv.w, y2.w);
            y3.x = fmaf(q3, xv.x, y3.x); y3.y = fmaf(q3, xv.y, y3.y);
            y3.z = fmaf(q3, xv.z, y3.z); y3.w = fmaf(q3, xv.w, y3.w);
        }
    }
#pragma unroll
    for (int o = 16; o > 0; o >>= 1) {
        den0 += __shfl_xor_sync(0xffffffffu, den0, o);
        den1 += __shfl_xor_sync(0xffffffffu, den1, o);
        den2 += __shfl_xor_sync(0xffffffffu, den2, o);
        den3 += __shfl_xor_sync(0xffffffffu, den3, o);
    }
    y0.x += __shfl_xor_sync(0xffffffffu, y0.x, 16); y0.y += __shfl_xor_sync(0xffffffffu, y0.y, 16);
    y0.z += __shfl_xor_sync(0xffffffffu, y0.z, 16); y0.w += __shfl_xor_sync(0xffffffffu, y0.w, 16);
    y1.x += __shfl_xor_sync(0xffffffffu, y1.x, 16); y1.y += __shfl_xor_sync(0xffffffffu, y1.y, 16);
    y1.z += __shfl_xor_sync(0xffffffffu, y1.z, 16); y1.w += __shfl_xor_sync(0xffffffffu, y1.w, 16);
    y2.x += __shfl_xor_sync(0xffffffffu, y2.x, 16); y2.y += __shfl_xor_sync(0xffffffffu, y2.y, 16);
    y2.z += __shfl_xor_sync(0xffffffffu, y2.z, 16); y2.w += __shfl_xor_sync(0xffffffffu, y2.w, 16);
    y3.x += __shfl_xor_sync(0xffffffffu, y3.x, 16); y3.y += __shfl_xor_sync(0xffffffffu, y3.y, 16);
    y3.z += __shfl_xor_sync(0xffffffffu, y3.z, 16); y3.w += __shfl_xor_sync(0xffffffffu, y3.w, 16);

    float4 asv = as4[w];
    float p0 = expf(leaky02(asv.x + adv.x));
    float p1 = expf(leaky02(asv.y + adv.y));
    float p2 = expf(leaky02(asv.z + adv.z));
    float p3 = expf(leaky02(asv.w + adv.w));
    den0 += p0; den1 += p1; den2 += p2; den3 += p3;
    if (lane < 16) {
        float4 xv = x4[(size_t)w * 16 + c];
        float r0 = 1.f / den0, r1 = 1.f / den1, r2 = 1.f / den2, r3 = 1.f / den3;
        float4* yr = reinterpret_cast<float4*>(y + (size_t)w * 256);
        yr[     c] = make_float4(fmaf(p0, xv.x, y0.x) * r0, fmaf(p0, xv.y, y0.y) * r0,
                                 fmaf(p0, xv.z, y0.z) * r0, fmaf(p0, xv.w, y0.w) * r0);
        yr[16 + c] = make_float4(fmaf(p1, xv.x, y1.x) * r1, fmaf(p1, xv.y, y1.y) * r1,
                                 fmaf(p1, xv.z, y1.z) * r1, fmaf(p1, xv.w, y1.w) * r1);
        yr[32 + c] = make_float4(fmaf(p2, xv.x, y2.x) * r2, fmaf(p2, xv.y, y2.y) * r2,
                                 fmaf(p2, xv.z, y2.z) * r2, fmaf(p2, xv.w, y2.w) * r2);
        yr[48 + c] = make_float4(fmaf(p3, xv.x, y3.x) * r3, fmaf(p3, xv.y, y3.y) * r3,
                                 fmaf(p3, xv.z, y3.z) * r3, fmaf(p3, xv.w, y3.w) * r3);
    }
}

// ---------------- fused pool + MLP ----------------
__global__ __launch_bounds__(64) void poolmlp_kernel(
    const float* __restrict__ x, const int* __restrict__ bptr,
    const float* __restrict__ l1w, const float* __restrict__ l1b,
    const float* __restrict__ l2w, const float* __restrict__ l2b,
    float* __restrict__ out)
{
    int b = blockIdx.x, t = threadIdx.x;
    int beg = bptr[b], end = bptr[b + 1];
    float sm = 0.f, mxv = 0.f;
    int i = beg;
    for (; i + 4 <= end; i += 4) {
        float v0 = x[(size_t)(i + 0) * HID + t];
        float v1 = x[(size_t)(i + 1) * HID + t];
        float v2 = x[(size_t)(i + 2) * HID + t];
        float v3 = x[(size_t)(i + 3) * HID + t];
        sm += (v0 + v1) + (v2 + v3);
        mxv = fmaxf(fmaxf(mxv, v0), fmaxf(v1, fmaxf(v2, v3)));
    }
    for (; i < end; i++) {
        float v = x[(size_t)i * HID + t];
        sm += v; mxv = fmaxf(mxv, v);
    }
    __shared__ float g[HID];
    __shared__ float hid[HID / 2];
    g[t] = (end > beg) ? (sm / (float)(end - beg) + mxv) : 0.f;
    __syncthreads();
    if (t < HID / 2) {
        float acc = l1b[t];
#pragma unroll 8
        for (int k = 0; k < HID; k++) acc = fmaf(g[k], l1w[k * (HID / 2) + t], acc);
        hid[t] = fmaxf(acc, 0.f);
    }
    __syncthreads();
    if (t < CLASSES) {
        float acc = l2b[t];
#pragma unroll
        for (int k = 0; k < HID / 2; k++) acc = fmaf(hid[k], l2w[k * CLASSES + t], acc);
        out[b * CLASSES + t] = acc;
    }
}

// ---------------- launch ----------------
static inline int gr(long t) { return (int)((t + 255) / 256); }

extern "C" void kernel_launch(void* const* d_in, const int* in_sizes, int n_in,
                              void* d_out, int out_size)
{
    const float* x_in  = (const float*)d_in[0];
    const int*   ei    = (const int*)  d_in[1];
    const int*   batch = (const int*)  d_in[2];
    const float* w0    = (const float*)d_in[3];
    const float* b0    = (const float*)d_in[4];
    const float* w1    = (const float*)d_in[5];
    const float* b1    = (const float*)d_in[6];
    const float* w2    = (const float*)d_in[7];
    const float* b2    = (const float*)d_in[8];
    const float* gat_w = (const float*)d_in[9];
    const float* att_s = (const float*)d_in[10];
    const float* att_d = (const float*)d_in[11];
    const float* gat_b = (const float*)d_in[12];
    const float* l1w   = (const float*)d_in[13];
    const float* l1b   = (const float*)d_in[14];
    const float* l2w   = (const float*)d_in[15];
    const float* l2b   = (const float*)d_in[16];
    float* out = (float*)d_out;

    const int* src = ei;
    const int* dst = ei + N_EDGES;

    float *h, *xb, *dinv, *asrc, *adst, *uv;
    int *counts, *rowptr, *cursor, *csr, *bsums, *boff, *bcnt, *bptr;
    cudaGetSymbolAddress((void**)&h,      g_h);
    cudaGetSymbolAddress((void**)&xb,     g_x);
    cudaGetSymbolAddress((void**)&counts, g_counts);
    cudaGetSymbolAddress((void**)&rowptr, g_rowptr);
    cudaGetSymbolAddress((void**)&cursor, g_cursor);
    cudaGetSymbolAddress((void**)&csr,    g_csrsrc);
    cudaGetSymbolAddress((void**)&bsums,  g_bsums);
    cudaGetSymbolAddress((void**)&boff,   g_boff);
    cudaGetSymbolAddress((void**)&bcnt,   g_bcnt);
    cudaGetSymbolAddress((void**)&bptr,   g_bptr);
    cudaGetSymbolAddress((void**)&dinv,   g_dinv);
    cudaGetSymbolAddress((void**)&asrc,   g_asrc);
    cudaGetSymbolAddress((void**)&adst,   g_adst);
    cudaGetSymbolAddress((void**)&uv,     g_uv);

    const int WPN_BLOCKS  = (N_NODES * 32 + 255) / 256;  // warp-per-node grids
    const int GEMM_BLOCKS = (N_NODES + 63) / 64;         // 782

    // ---- setup, ordered so the 4th launch is the first (K=128) GEMM ----
    zero_kernel<<<gr(N_NODES), 256>>>(counts, N_NODES, bcnt, NGRAPH);                 // 1
    hist_kernel<<<gr(N_EDGES), 256>>>(dst, counts, batch, bcnt, N_EDGES, N_NODES);    // 2
    scan_local_kernel<<<NB_SCAN, 1024>>>(counts, rowptr, bsums, dinv, N_NODES);       // 3
    gemm256<128, true, false, false><<<GEMM_BLOCKS, 256>>>(                           // 4 (profiled)
        x_in, w0, h, HID, dinv, nullptr, N_NODES);
    uv_kernel<<<1, 256>>>(gat_w, att_s, att_d, uv);                                   // 5
    scan_small2_kernel<<<2, 1024>>>(bsums, boff, NB_SCAN, bcnt, bptr, NGRAPH);        // 6
    scan_apply_kernel<<<gr(N_NODES + 1), 256>>>(rowptr, cursor, boff, N_NODES);       // 7
    scatter_kernel<<<gr(N_EDGES), 256>>>(src, dst, cursor, csr, N_EDGES);             // 8

    // ---- GCN layers ----
    gcn_gather_kernel<false><<<WPN_BLOCKS, 256>>>(
        h, rowptr, csr, dinv, b0, xb, nullptr, nullptr, nullptr, N_NODES);

    gemm256<64, true, false, false><<<GEMM_BLOCKS, 256>>>(
        xb, w1, h, HID, dinv, nullptr, N_NODES);
    gcn_gather_kernel<false><<<WPN_BLOCKS, 256>>>(
        h, rowptr, csr, dinv, b1, xb, nullptr, nullptr, nullptr, N_NODES);

    gemm256<64, true, false, false><<<GEMM_BLOCKS, 256>>>(
        xb, w2, h, HID, dinv, nullptr, N_NODES);
    gcn_gather_kernel<true><<<WPN_BLOCKS, 256>>>(
        h, rowptr, csr, dinv, b2, xb, uv, asrc, adst, N_NODES);

    // ---- GAT in x-space ----
    gat_gather_kernel<<<WPN_BLOCKS, 256>>>(xb, asrc, adst, rowptr, csr, h, N_NODES);
    gemm256<256, false, true, true><<<GEMM_BLOCKS, 256>>>(
        h, gat_w, xb, HID, nullptr, gat_b, N_NODES);

    // ---- fused pool + MLP ----
    poolmlp_kernel<<<NGRAPH, 64>>>(xb, bptr, l1w, l1b, l2w, l2b, out);
}

// round 9
// speedup vs baseline: 1.3572x; 1.3572x over previous
#include <cuda_runtime.h>
#include <cuda_bf16.h>
#include <cuda_fp16.h>
#include <math.h>

#define N_NODES 50000
#define N_EDGES 800000
#define F_IN    128
#define HID     64
#define HEADS   4
#define NGRAPH  512
#define CLASSES 2
#define NB_SCAN ((N_NODES + 1023) >> 10)   // 49

// ---------------- scratch (static device globals; no allocation) ----------------
__device__ float g_h[(size_t)N_NODES * 256];     // GCN hs [N,64] fp16 / GAT y [N,256] fp32
__device__ float g_x[(size_t)N_NODES * HID];
__device__ int   g_counts[N_NODES];
__device__ int   g_rowptr[N_NODES + 1];
__device__ int   g_cursor[N_NODES];
__device__ int   g_csrsrc[N_EDGES];
__device__ int   g_bsums[64];
__device__ int   g_boff[65];
__device__ int   g_bcnt[NGRAPH];
__device__ int   g_bptr[NGRAPH + 1];
__device__ float g_dinv[N_NODES];
__device__ float g_asrc[N_NODES * HEADS];
__device__ float g_adst[N_NODES * HEADS];
__device__ float g_uv[512];                      // u[4][64] then v[4][64]

// ---------------- helpers ----------------
__device__ __forceinline__ float leaky02(float v) { return v > 0.f ? v : 0.2f * v; }

__device__ __forceinline__ unsigned long long packdup(float x) {
    unsigned long long r;
    asm("mov.b64 %0, {%1, %1};" : "=l"(r) : "f"(x));
    return r;
}
__device__ __forceinline__ void ffma2(unsigned long long& d, unsigned long long a, unsigned long long b) {
    asm("fma.rn.f32x2 %0, %1, %2, %3;" : "=l"(d) : "l"(a), "l"(b), "l"(d));
}
__device__ __forceinline__ float2 unpack2(unsigned long long v) {
    float2 r;
    asm("mov.b64 {%0, %1}, %2;" : "=f"(r.x), "=f"(r.y) : "l"(v));
    return r;
}

// ---------------- init / CSR build ----------------
__global__ void zero_kernel(int* a, int na, int* b, int nb) {
    int i = blockIdx.x * blockDim.x + threadIdx.x;
    if (i < na) a[i] = 0;
    if (i < nb) b[i] = 0;
}
__global__ void hist_kernel(const int* __restrict__ dst, int* cnt,
                            const int* __restrict__ batch, int* bcnt, int E, int N) {
    int e = blockIdx.x * blockDim.x + threadIdx.x;
    if (e < E) atomicAdd(&cnt[dst[e]], 1);
    if (e < N) atomicAdd(&bcnt[batch[e]], 1);
}

// u_h = W_h @ att_src[h], v_h = W_h @ att_dst[h]  (one 256-thread block)
__global__ __launch_bounds__(256) void uv_kernel(
    const float* __restrict__ gat_w, const float* __restrict__ att_s,
    const float* __restrict__ att_d, float* __restrict__ uv)
{
    int t = threadIdx.x;
    int h = t >> 6, k = t & 63;
    const float* wrow = gat_w + (size_t)k * 256 + h * 64;
    const float* as = att_s + h * 64;
    const float* ad = att_d + h * 64;
    float su = 0.f, sv = 0.f;
#pragma unroll 8
    for (int c = 0; c < 64; c++) {
        float w = wrow[c];
        su = fmaf(w, as[c], su);
        sv = fmaf(w, ad[c], sv);
    }
    uv[h * 64 + k] = su;
    uv[256 + h * 64 + k] = sv;
}

// per-1024-chunk local exclusive scan + block sums + dinv (fused)
__global__ __launch_bounds__(1024) void scan_local_kernel(
    const int* __restrict__ counts, int* rowptr, int* bsums, float* dinv, int n)
{
    __shared__ int wsum[32];
    int tid = threadIdx.x, lane = tid & 31, wid = tid >> 5;
    int idx = blockIdx.x * 1024 + tid;
    int v = (idx < n) ? counts[idx] : 0;
    if (idx < n) dinv[idx] = rsqrtf((float)(v + 1));
    int inc = v;
#pragma unroll
    for (int o = 1; o < 32; o <<= 1) {
        int t = __shfl_up_sync(0xffffffffu, inc, o);
        if (lane >= o) inc += t;
    }
    if (lane == 31) wsum[wid] = inc;
    __syncthreads();
    if (wid == 0) {
        int wi = wsum[lane];
#pragma unroll
        for (int o = 1; o < 32; o <<= 1) {
            int t = __shfl_up_sync(0xffffffffu, wi, o);
            if (lane >= o) wi += t;
        }
        wsum[lane] = wi;
    }
    __syncthreads();
    int excl = inc - v + (wid ? wsum[wid - 1] : 0);
    if (idx < n) rowptr[idx] = excl;
    if (tid == 1023) bsums[blockIdx.x] = excl + v;
}

// two independent small exclusive scans in one launch
__global__ __launch_bounds__(1024) void scan_small2_kernel(
    const int* __restrict__ in0, int* out0, int n0,
    const int* __restrict__ in1, int* out1, int n1)
{
    __shared__ int wsum[32];
    const int* in = blockIdx.x ? in1 : in0;
    int*      out = blockIdx.x ? out1 : out0;
    int         n = blockIdx.x ? n1 : n0;
    int tid = threadIdx.x, lane = tid & 31, wid = tid >> 5;
    int v = (tid < n) ? in[tid] : 0;
    int inc = v;
#pragma unroll
    for (int o = 1; o < 32; o <<= 1) {
        int t = __shfl_up_sync(0xffffffffu, inc, o);
        if (lane >= o) inc += t;
    }
    if (lane == 31) wsum[wid] = inc;
    __syncthreads();
    if (wid == 0) {
        int wi = wsum[lane];
#pragma unroll
        for (int o = 1; o < 32; o <<= 1) {
            int t = __shfl_up_sync(0xffffffffu, wi, o);
            if (lane >= o) wi += t;
        }
        wsum[lane] = wi;
    }
    __syncthreads();
    int excl = inc - v + (wid ? wsum[wid - 1] : 0);
    if (tid < n) out[tid] = excl;
    if (tid == n - 1) out[n] = excl + v;
}

__global__ void scan_apply_kernel(int* rowptr, int* cursor, const int* __restrict__ boff, int n) {
    int idx = blockIdx.x * blockDim.x + threadIdx.x;
    if (idx < n) {
        int r = rowptr[idx] + boff[idx >> 10];
        rowptr[idx] = r;
        cursor[idx] = r;
    }
    if (idx == n) rowptr[n] = boff[NB_SCAN];
}

__global__ void scatter_kernel(const int* __restrict__ src, const int* __restrict__ dst,
                               int* cursor, int* __restrict__ csr, int E)
{
    int e = blockIdx.x * blockDim.x + threadIdx.x;
    if (e >= E) return;
    int p = atomicAdd(&cursor[dst[e]], 1);
    csr[p] = src[e];
}

// ---------------- GEMM: Y = X(N,K) @ W -> [N,64], BM=128, 256 thr, 4x8 tile ----------------
// SCALE: scale output row by dinv[row]. PERMW: GAT head-permuted W.
// RELUB: v = relu(v*0.25 + bias). OUTH: store output as fp16 (__half, row stride 64).
template <int K, bool SCALE, bool PERMW, bool RELUB, bool OUTH>
__global__ __launch_bounds__(256) void gemm256(
    const float* __restrict__ X, const float* __restrict__ W,
    float* __restrict__ Y, int ldy, const float* __restrict__ dinv,
    const float* __restrict__ bias, int n)
{
    __shared__ float Xs[16][128];
    __shared__ float Ws[16][64];
    int tid = threadIdx.x;
    int tx = tid & 7;        // col group: cols tx*8 .. +7
    int ty = tid >> 3;       // 0..31  : rows ty*4 .. +3
    int row0 = blockIdx.x * 128;

    unsigned long long acc2[4][4];
#pragma unroll
    for (int i = 0; i < 4; i++)
#pragma unroll
        for (int j = 0; j < 4; j++) acc2[i][j] = 0ull;

    int lrow  = tid >> 1;
    int lhalf = tid & 1;
    int xrow = min(row0 + lrow, n - 1);
    const float4* xr = reinterpret_cast<const float4*>(X + (size_t)xrow * K);

    int wk = tid >> 4;
    int wc = (tid & 15) * 4;

    for (int k0 = 0; k0 < K; k0 += 16) {
        int i0 = (k0 >> 2) + lhalf * 2;
        float4 a = xr[i0], b = xr[i0 + 1];
        int kb = lhalf * 8;
        Xs[kb + 0][lrow] = a.x; Xs[kb + 1][lrow] = a.y;
        Xs[kb + 2][lrow] = a.z; Xs[kb + 3][lrow] = a.w;
        Xs[kb + 4][lrow] = b.x; Xs[kb + 5][lrow] = b.y;
        Xs[kb + 6][lrow] = b.z; Xs[kb + 7][lrow] = b.w;
        if (PERMW) {
            int k = k0 + wk;
            int c = k & 63, hh = k >> 6;
            *reinterpret_cast<float4*>(&Ws[wk][wc]) =
                *reinterpret_cast<const float4*>(&W[(size_t)c * 256 + hh * 64 + wc]);
        } else {
            *reinterpret_cast<float4*>(&Ws[wk][wc]) =
                *reinterpret_cast<const float4*>(&W[(size_t)(k0 + wk) * 64 + wc]);
        }
        __syncthreads();
#pragma unroll
        for (int k = 0; k < 16; k++) {
            float4 xv = *reinterpret_cast<const float4*>(&Xs[k][ty * 4]);
            const unsigned long long* wp = reinterpret_cast<const unsigned long long*>(&Ws[k][tx * 8]);
            unsigned long long w0 = wp[0], w1 = wp[1], w2 = wp[2], w3 = wp[3];
            unsigned long long xd;
            xd = packdup(xv.x);
            ffma2(acc2[0][0], xd, w0); ffma2(acc2[0][1], xd, w1);
            ffma2(acc2[0][2], xd, w2); ffma2(acc2[0][3], xd, w3);
            xd = packdup(xv.y);
            ffma2(acc2[1][0], xd, w0); ffma2(acc2[1][1], xd, w1);
            ffma2(acc2[1][2], xd, w2); ffma2(acc2[1][3], xd, w3);
            xd = packdup(xv.z);
            ffma2(acc2[2][0], xd, w0); ffma2(acc2[2][1], xd, w1);
            ffma2(acc2[2][2], xd, w2); ffma2(acc2[2][3], xd, w3);
            xd = packdup(xv.w);
            ffma2(acc2[3][0], xd, w0); ffma2(acc2[3][1], xd, w1);
            ffma2(acc2[3][2], xd, w2); ffma2(acc2[3][3], xd, w3);
        }
        __syncthreads();
    }

    float bv[8];
    if (RELUB) {
#pragma unroll
        for (int j = 0; j < 8; j++) bv[j] = bias[tx * 8 + j];
    }

#pragma unroll
    for (int i = 0; i < 4; i++) {
        int r = row0 + ty * 4 + i;
        float v[8];
#pragma unroll
        for (int jp = 0; jp < 4; jp++) {
            float2 p = unpack2(acc2[i][jp]);
            v[jp * 2] = p.x; v[jp * 2 + 1] = p.y;
        }
        if (r < n) {
            if (SCALE) {
                float s = dinv[r];
#pragma unroll
                for (int j = 0; j < 8; j++) v[j] *= s;
            }
            if (RELUB) {
#pragma unroll
                for (int j = 0; j < 8; j++) v[j] = fmaxf(fmaf(v[j], 0.25f, bv[j]), 0.f);
            }
            if (OUTH) {
                __half2 hh[4];
#pragma unroll
                for (int jp = 0; jp < 4; jp++)
                    hh[jp] = __floats2half2_rn(v[jp * 2], v[jp * 2 + 1]);
                __half* yh = reinterpret_cast<__half*>(Y) + (size_t)r * 64 + tx * 8;
                *reinterpret_cast<float4*>(yh) = *reinterpret_cast<float4*>(hh);
            } else {
                float* yr = Y + (size_t)r * ldy + tx * 8;
                reinterpret_cast<float4*>(yr)[0] = make_float4(v[0], v[1], v[2], v[3]);
                reinterpret_cast<float4*>(yr)[1] = make_float4(v[4], v[5], v[6], v[7]);
            }
        }
    }
}

// ---------------- GCN gather (fp16 payload): out[d] = relu(dinv[d]*(sum hs[s] + hs[d]) + b) ----
// hs is fp16 [N,64] (dinv[src] folded in by GEMM epilogue). fp32 accumulation.
template <bool ATT>
__global__ __launch_bounds__(256) void gcn_gather_kernel(
    const float* __restrict__ hs_raw, const int* __restrict__ rowptr, const int* __restrict__ csr,
    const float* __restrict__ dinv, const float* __restrict__ bias,
    float* __restrict__ xout, const float* __restrict__ uv,
    float* __restrict__ asrc, float* __restrict__ adst, int n)
{
    __shared__ float2 suv[256];
    if (ATT) {
        suv[threadIdx.x] = reinterpret_cast<const float2*>(uv)[threadIdx.x];
        __syncthreads();
    }

    int w = (blockIdx.x * blockDim.x + threadIdx.x) >> 5;
    if (w >= n) return;
    int lane = threadIdx.x & 31;
    int beg = rowptr[w], end = rowptr[w + 1];
    const __half2* h2 = reinterpret_cast<const __half2*>(hs_raw);
    float2 acc = make_float2(0.f, 0.f);
    for (int base = beg; base < end; base += 32) {
        int m = min(32, end - base);
        int sreg = (base + lane < end) ? csr[base + lane] : 0;
        int i = 0;
        for (; i + 4 <= m; i += 4) {
            int s0 = __shfl_sync(0xffffffffu, sreg, i);
            int s1 = __shfl_sync(0xffffffffu, sreg, i + 1);
            int s2 = __shfl_sync(0xffffffffu, sreg, i + 2);
            int s3 = __shfl_sync(0xffffffffu, sreg, i + 3);
            float2 v0 = __half22float2(h2[(size_t)s0 * 32 + lane]);
            float2 v1 = __half22float2(h2[(size_t)s1 * 32 + lane]);
            float2 v2 = __half22float2(h2[(size_t)s2 * 32 + lane]);
            float2 v3 = __half22float2(h2[(size_t)s3 * 32 + lane]);
            acc.x += (v0.x + v1.x) + (v2.x + v3.x);
            acc.y += (v0.y + v1.y) + (v2.y + v3.y);
        }
        for (; i < m; i++) {
            int s = __shfl_sync(0xffffffffu, sreg, i);
            float2 v = __half22float2(h2[(size_t)s * 32 + lane]);
            acc.x += v.x; acc.y += v.y;
        }
    }
    float2 sv = __half22float2(h2[(size_t)w * 32 + lane]);
    float dw = dinv[w];
    float2 bv = reinterpret_cast<const float2*>(bias)[lane];
    float2 o;
    o.x = fmaxf((acc.x + sv.x) * dw + bv.x, 0.f);
    o.y = fmaxf((acc.y + sv.y) * dw + bv.y, 0.f);
    reinterpret_cast<float2*>(xout + (size_t)w * HID)[lane] = o;

    if (ATT) {
        float a0 = o.x * suv[      lane].x + o.y * suv[      lane].y;
        float a1 = o.x * suv[ 32 + lane].x + o.y * suv[ 32 + lane].y;
        float a2 = o.x * suv[ 64 + lane].x + o.y * suv[ 64 + lane].y;
        float a3 = o.x * suv[ 96 + lane].x + o.y * suv[ 96 + lane].y;
        float d0 = o.x * suv[128 + lane].x + o.y * suv[128 + lane].y;
        float d1 = o.x * suv[160 + lane].x + o.y * suv[160 + lane].y;
        float d2 = o.x * suv[192 + lane].x + o.y * suv[192 + lane].y;
        float d3 = o.x * suv[224 + lane].x + o.y * suv[224 + lane].y;
#pragma unroll
        for (int off = 16; off > 0; off >>= 1) {
            a0 += __shfl_xor_sync(0xffffffffu, a0, off);
            a1 += __shfl_xor_sync(0xffffffffu, a1, off);
            a2 += __shfl_xor_sync(0xffffffffu, a2, off);
            a3 += __shfl_xor_sync(0xffffffffu, a3, off);
            d0 += __shfl_xor_sync(0xffffffffu, d0, off);
            d1 += __shfl_xor_sync(0xffffffffu, d1, off);
            d2 += __shfl_xor_sync(0xffffffffu, d2, off);
            d3 += __shfl_xor_sync(0xffffffffu, d3, off);
        }
        if (lane == 0) {
            reinterpret_cast<float4*>(asrc)[w] = make_float4(a0, a1, a2, a3);
            reinterpret_cast<float4*>(adst)[w] = make_float4(d0, d1, d2, d3);
        }
    }
}

// ---------------- GAT gather (x-space, fp32): y[d,h,:] = (sum p_h x[s] + p_h^self x[d])/den_h --
// No-shift softmax: e-values are O(0.01) here, exp cannot overflow.
__global__ __launch_bounds__(256) void gat_gather_kernel(
    const float* __restrict__ x, const float* __restrict__ asrc, const float* __restrict__ adst,
    const int* __restrict__ rowptr, const int* __restrict__ csr,
    float* __restrict__ y, int n)
{
    int w = (blockIdx.x * blockDim.x + threadIdx.x) >> 5;
    if (w >= n) return;
    int lane = threadIdx.x & 31;
    int beg = rowptr[w], end = rowptr[w + 1];

    float4 adv = reinterpret_cast<const float4*>(adst)[w];
    const float2* x2 = reinterpret_cast<const float2*>(x);
    const float4* as4 = reinterpret_cast<const float4*>(asrc);

    float2 y0 = make_float2(0.f, 0.f), y1 = y0, y2 = y0, y3 = y0;
    float den0 = 0.f, den1 = 0.f, den2 = 0.f, den3 = 0.f;

    for (int base = beg; base < end; base += 32) {
        int m = min(32, end - base);
        bool valid = (base + lane < end);
        int sreg = valid ? csr[base + lane] : 0;
        float4 as = as4[sreg];
        float p0 = valid ? expf(leaky02(as.x + adv.x)) : 0.f;
        float p1 = valid ? expf(leaky02(as.y + adv.y)) : 0.f;
        float p2 = valid ? expf(leaky02(as.z + adv.z)) : 0.f;
        float p3 = valid ? expf(leaky02(as.w + adv.w)) : 0.f;
        den0 += p0; den1 += p1; den2 += p2; den3 += p3;
        for (int i = 0; i < m; i++) {
            int   s  = __shfl_sync(0xffffffffu, sreg, i);
            float q0 = __shfl_sync(0xffffffffu, p0, i);
            float q1 = __shfl_sync(0xffffffffu, p1, i);
            float q2 = __shfl_sync(0xffffffffu, p2, i);
            float q3 = __shfl_sync(0xffffffffu, p3, i);
            float2 xv = x2[(size_t)s * 32 + lane];
            y0.x = fmaf(q0, xv.x, y0.x); y0.y = fmaf(q0, xv.y, y0.y);
            y1.x = fmaf(q1, xv.x, y1.x); y1.y = fmaf(q1, xv.y, y1.y);
            y2.x = fmaf(q2, xv.x, y2.x); y2.y = fmaf(q2, xv.y, y2.y);
            y3.x = fmaf(q3, xv.x, y3.x); y3.y = fmaf(q3, xv.y, y3.y);
        }
    }
#pragma unroll
    for (int o = 16; o > 0; o >>= 1) {
        den0 += __shfl_xor_sync(0xffffffffu, den0, o);
        den1 += __shfl_xor_sync(0xffffffffu, den1, o);
        den2 += __shfl_xor_sync(0xffffffffu, den2, o);
        den3 += __shfl_xor_sync(0xffffffffu, den3, o);
    }
    // self-loop
    {
        float4 asv = as4[w];
        float p0 = expf(leaky02(asv.x + adv.x));
        float p1 = expf(leaky02(asv.y + adv.y));
        float p2 = expf(leaky02(asv.z + adv.z));
        float p3 = expf(leaky02(asv.w + adv.w));
        den0 += p0; den1 += p1; den2 += p2; den3 += p3;
        float2 xv = x2[(size_t)w * 32 + lane];
        y0.x = fmaf(p0, xv.x, y0.x); y0.y = fmaf(p0, xv.y, y0.y);
        y1.x = fmaf(p1, xv.x, y1.x); y1.y = fmaf(p1, xv.y, y1.y);
        y2.x = fmaf(p2, xv.x, y2.x); y2.y = fmaf(p2, xv.y, y2.y);
        y3.x = fmaf(p3, xv.x, y3.x); y3.y = fmaf(p3, xv.y, y3.y);
    }
    float r0 = 1.f / den0, r1 = 1.f / den1, r2 = 1.f / den2, r3 = 1.f / den3;
    float2* yr = reinterpret_cast<float2*>(y + (size_t)w * 256);
    yr[      lane] = make_float2(y0.x * r0, y0.y * r0);
    yr[ 32 + lane] = make_float2(y1.x * r1, y1.y * r1);
    yr[ 64 + lane] = make_float2(y2.x * r2, y2.y * r2);
    yr[ 96 + lane] = make_float2(y3.x * r3, y3.y * r3);
}

// ---------------- fused pool + MLP (one 64-thread block per graph; batch sorted) ----------------
__global__ __launch_bounds__(64) void poolmlp_kernel(
    const float* __restrict__ x, const int* __restrict__ bptr,
    const float* __restrict__ l1w, const float* __restrict__ l1b,
    const float* __restrict__ l2w, const float* __restrict__ l2b,
    float* __restrict__ out)
{
    int b = blockIdx.x, t = threadIdx.x;
    int beg = bptr[b], end = bptr[b + 1];
    float sm = 0.f, mxv = 0.f;
    int i = beg;
    for (; i + 4 <= end; i += 4) {
        float v0 = x[(size_t)(i + 0) * HID + t];
        float v1 = x[(size_t)(i + 1) * HID + t];
        float v2 = x[(size_t)(i + 2) * HID + t];
        float v3 = x[(size_t)(i + 3) * HID + t];
        sm += (v0 + v1) + (v2 + v3);
        mxv = fmaxf(fmaxf(mxv, v0), fmaxf(v1, fmaxf(v2, v3)));
    }
    for (; i < end; i++) {
        float v = x[(size_t)i * HID + t];
        sm += v; mxv = fmaxf(mxv, v);
    }
    __shared__ float g[HID];
    __shared__ float hid[HID / 2];
    g[t] = (end > beg) ? (sm / (float)(end - beg) + mxv) : 0.f;
    __syncthreads();
    if (t < HID / 2) {
        float acc = l1b[t];
#pragma unroll 8
        for (int k = 0; k < HID; k++) acc = fmaf(g[k], l1w[k * (HID / 2) + t], acc);
        hid[t] = fmaxf(acc, 0.f);
    }
    __syncthreads();
    if (t < CLASSES) {
        float acc = l2b[t];
#pragma unroll
        for (int k = 0; k < HID / 2; k++) acc = fmaf(hid[k], l2w[k * CLASSES + t], acc);
        out[b * CLASSES + t] = acc;
    }
}

// ---------------- launch ----------------
static inline int gr(long t) { return (int)((t + 255) / 256); }

extern "C" void kernel_launch(void* const* d_in, const int* in_sizes, int n_in,
                              void* d_out, int out_size)
{
    const float* x_in  = (const float*)d_in[0];
    const int*   ei    = (const int*)  d_in[1];
    const int*   batch = (const int*)  d_in[2];
    const float* w0    = (const float*)d_in[3];
    const float* b0    = (const float*)d_in[4];
    const float* w1    = (const float*)d_in[5];
    const float* b1    = (const float*)d_in[6];
    const float* w2    = (const float*)d_in[7];
    const float* b2    = (const float*)d_in[8];
    const float* gat_w = (const float*)d_in[9];
    const float* att_s = (const float*)d_in[10];
    const float* att_d = (const float*)d_in[11];
    const float* gat_b = (const float*)d_in[12];
    const float* l1w   = (const float*)d_in[13];
    const float* l1b   = (const float*)d_in[14];
    const float* l2w   = (const float*)d_in[15];
    const float* l2b   = (const float*)d_in[16];
    float* out = (float*)d_out;

    const int* src = ei;
    const int* dst = ei + N_EDGES;

    float *h, *xb, *dinv, *asrc, *adst, *uv;
    int *counts, *rowptr, *cursor, *csr, *bsums, *boff, *bcnt, *bptr;
    cudaGetSymbolAddress((void**)&h,      g_h);
    cudaGetSymbolAddress((void**)&xb,     g_x);
    cudaGetSymbolAddress((void**)&counts, g_counts);
    cudaGetSymbolAddress((void**)&rowptr, g_rowptr);
    cudaGetSymbolAddress((void**)&cursor, g_cursor);
    cudaGetSymbolAddress((void**)&csr,    g_csrsrc);
    cudaGetSymbolAddress((void**)&bsums,  g_bsums);
    cudaGetSymbolAddress((void**)&boff,   g_boff);
    cudaGetSymbolAddress((void**)&bcnt,   g_bcnt);
    cudaGetSymbolAddress((void**)&bptr,   g_bptr);
    cudaGetSymbolAddress((void**)&dinv,   g_dinv);
    cudaGetSymbolAddress((void**)&asrc,   g_asrc);
    cudaGetSymbolAddress((void**)&adst,   g_adst);
    cudaGetSymbolAddress((void**)&uv,     g_uv);

    const int WPN_BLOCKS = (N_NODES * 32 + 255) / 256;   // warp-per-node grids
    const int GEMM_ROWS  = (N_NODES + 127) / 128;        // 391

    // ---- setup, ordered so the 4th launch is the first (K=128) GEMM ----
    zero_kernel<<<gr(N_NODES), 256>>>(counts, N_NODES, bcnt, NGRAPH);                 // 1
    hist_kernel<<<gr(N_EDGES), 256>>>(dst, counts, batch, bcnt, N_EDGES, N_NODES);    // 2
    scan_local_kernel<<<NB_SCAN, 1024>>>(counts, rowptr, bsums, dinv, N_NODES);       // 3
    gemm256<128, true, false, false, true><<<GEMM_ROWS, 256>>>(                       // 4 (profiled)
        x_in, w0, h, HID, dinv, nullptr, N_NODES);
    uv_kernel<<<1, 256>>>(gat_w, att_s, att_d, uv);                                   // 5
    scan_small2_kernel<<<2, 1024>>>(bsums, boff, NB_SCAN, bcnt, bptr, NGRAPH);        // 6
    scan_apply_kernel<<<gr(N_NODES + 1), 256>>>(rowptr, cursor, boff, N_NODES);       // 7
    scatter_kernel<<<gr(N_EDGES), 256>>>(src, dst, cursor, csr, N_EDGES);             // 8

    // ---- GCN layers (fp16 hs intermediates) ----
    gcn_gather_kernel<false><<<WPN_BLOCKS, 256>>>(
        h, rowptr, csr, dinv, b0, xb, nullptr, nullptr, nullptr, N_NODES);

    gemm256<64, true, false, false, true><<<GEMM_ROWS, 256>>>(
        xb, w1, h, HID, dinv, nullptr, N_NODES);
    gcn_gather_kernel<false><<<WPN_BLOCKS, 256>>>(
        h, rowptr, csr, dinv, b1, xb, nullptr, nullptr, nullptr, N_NODES);

    gemm256<64, true, false, false, true><<<GEMM_ROWS, 256>>>(
        xb, w2, h, HID, dinv, nullptr, N_NODES);
    gcn_gather_kernel<true><<<WPN_BLOCKS, 256>>>(
        h, rowptr, csr, dinv, b2, xb, uv, asrc, adst, N_NODES);

    // ---- GAT in x-space (fp32): gather weighted x into y [N,256], then recombine GEMM ----
    gat_gather_kernel<<<WPN_BLOCKS, 256>>>(xb, asrc, adst, rowptr, csr, h, N_NODES);
    gemm256<256, false, true, true, false><<<GEMM_ROWS, 256>>>(
        h, gat_w, xb, HID, nullptr, gat_b, N_NODES);

    // ---- fused pool + MLP ----
    poolmlp_kernel<<<NGRAPH, 64>>>(xb, bptr, l1w, l1b, l2w, l2b, out);
}